// round 14
// baseline (speedup 1.0000x reference)
#include <cuda_runtime.h>
#include <cuda_bf16.h>
#include <math.h>
#include <stdint.h>

#define D      256
#define N1C    40000
#define N2C    8000
#define NTOT   (N1C + N2C)
#define CAP    96            // bucket capacity; Poisson(25) tail @96 ~ 2e-27
#define KEXP   1536          // expanded K:  [Ah|Ah|Al] x [Wh;Wl;Wh]
#define KSTORE 1024          // Aexp stored dedup'd: [Ah|Al]
#define BM     128
#define BN     128
#define KC     64
#define NCHUNK 24            // 1536/64
#define STAGES 3
#define STAGE_BYTES (BM*128 + BN*128)       // 32 KB
#define SMEM_BYTES  (STAGES*STAGE_BYTES + 1024)

// ---------------- scratch ----------------
__device__ float g_h1[(size_t)N1C * D];
__device__ __nv_bfloat16 g_Aexp[(size_t)N1C * KSTORE];   // 81.9 MB (reused layer 2)
__device__ __nv_bfloat16 g_Wb1[(size_t)D * KEXP];
__device__ __nv_bfloat16 g_Wb2[(size_t)D * KEXP];
__device__ int g_cur[NTOT];                     // zero at steady state (self-cleaning)
__device__ int g_ssrc[(size_t)NTOT * CAP];      // fixed-capacity buckets, 18.4 MB

// ---------------- helpers ----------------
__device__ __forceinline__ uint32_t smem_u32(const void* p) {
    uint32_t a;
    asm("{ .reg .u64 t; cvta.to.shared.u64 t, %1; cvt.u32.u64 %0, t; }"
        : "=r"(a) : "l"(p));
    return a;
}
#define SWZ(o) ((o) ^ (((o) >> 3) & 0x70))

__device__ __forceinline__ void cp_async16(uint32_t dst, const void* src) {
    asm volatile("cp.async.cg.shared.global [%0], [%1], 16;" :: "r"(dst), "l"(src));
}
#define CP_COMMIT()  asm volatile("cp.async.commit_group;")
#define CP_WAIT(n)   asm volatile("cp.async.wait_group %0;" :: "n"(n))

__device__ __forceinline__ void ldsm_x4(uint32_t& r0, uint32_t& r1,
                                        uint32_t& r2, uint32_t& r3, uint32_t addr) {
    asm volatile("ldmatrix.sync.aligned.m8n8.x4.shared.b16 {%0,%1,%2,%3}, [%4];"
                 : "=r"(r0), "=r"(r1), "=r"(r2), "=r"(r3) : "r"(addr));
}
__device__ __forceinline__ void mma_bf16(float* c,
        uint32_t a0, uint32_t a1, uint32_t a2, uint32_t a3,
        uint32_t b0, uint32_t b1) {
    asm volatile(
        "mma.sync.aligned.m16n8k16.row.col.f32.bf16.bf16.f32 "
        "{%0,%1,%2,%3}, {%4,%5,%6,%7}, {%8,%9}, {%0,%1,%2,%3};"
        : "+f"(c[0]), "+f"(c[1]), "+f"(c[2]), "+f"(c[3])
        : "r"(a0), "r"(a1), "r"(a2), "r"(a3), "r"(b0), "r"(b1));
}

// ---------------- direct bucket binning (replaces hist+scan+bin) ----------------
// Combined index space: layer-1 dst in [0,N1C), layer-2 dst in [N1C, NTOT).
// cur[] must be zero at entry (zero-init at load; agg_prep self-cleans per replay).
__global__ void bin12_kernel(const int* __restrict__ src1, const int* __restrict__ dst1, int E1,
                             const int* __restrict__ src2, const int* __restrict__ dst2, int E2,
                             int* __restrict__ cur, int* __restrict__ ssrc) {
    const int t = blockIdx.x * blockDim.x + threadIdx.x;
    if (t < E1) {
        int d = __ldg(dst1 + t);
        int p = atomicAdd(cur + d, 1);
        if (p < CAP) ssrc[(size_t)d * CAP + p] = __ldg(src1 + t);
    } else if (t < E1 + E2) {
        int e = t - E1;
        int d = N1C + __ldg(dst2 + e);
        int p = atomicAdd(cur + d, 1);
        if (p < CAP) ssrc[(size_t)d * CAP + p] = __ldg(src2 + e);
    }
}

// ---------------- fused aggregation + mean + bf16-split prep ----------------
// warp per dst node; self-cleans cur[]. base = 0 (layer1) or N1C (layer2).
__device__ __forceinline__ void split4(float4 v, ushort4& hi, ushort4& lo) {
    float f[4] = {v.x, v.y, v.z, v.w};
    unsigned short* hp = &hi.x;
    unsigned short* lp = &lo.x;
    #pragma unroll
    for (int t = 0; t < 4; t++) {
        __nv_bfloat16 h = __float2bfloat16(f[t]);
        __nv_bfloat16 l = __float2bfloat16(f[t] - __bfloat162float(h));
        hp[t] = *(unsigned short*)&h;
        lp[t] = *(unsigned short*)&l;
    }
}
__device__ __forceinline__ void acc4(float4& a, float4 v) {
    a.x += v.x; a.y += v.y; a.z += v.z; a.w += v.w;
}

__global__ void agg_prep_kernel(const float* __restrict__ x,
                                int* __restrict__ cur,
                                const int* __restrict__ ssrc,
                                __nv_bfloat16* __restrict__ Aexp, int n, int base) {
    const int d = (blockIdx.x * blockDim.x + threadIdx.x) >> 5;
    const int lane = threadIdx.x & 31;
    if (d >= n) return;
    const int node = base + d;
    int deg = __ldg(cur + node);
    if (lane == 0) cur[node] = 0;            // self-clean for next replay
    if (deg > CAP) deg = CAP;

    const int beg = node * CAP;
    const int end = beg + deg;

    float4 a0 = make_float4(0, 0, 0, 0), a1 = make_float4(0, 0, 0, 0);
    int e = beg;
    for (; e + 4 <= end; e += 4) {
        int s0 = __ldg(ssrc + e + 0);
        int s1 = __ldg(ssrc + e + 1);
        int s2 = __ldg(ssrc + e + 2);
        int s3 = __ldg(ssrc + e + 3);
        const float4* p0 = (const float4*)(x + (size_t)s0 * D);
        const float4* p1 = (const float4*)(x + (size_t)s1 * D);
        const float4* p2 = (const float4*)(x + (size_t)s2 * D);
        const float4* p3 = (const float4*)(x + (size_t)s3 * D);
        float4 u00 = __ldg(p0 + lane),      u01 = __ldg(p0 + lane + 32);
        float4 u10 = __ldg(p1 + lane),      u11 = __ldg(p1 + lane + 32);
        float4 u20 = __ldg(p2 + lane),      u21 = __ldg(p2 + lane + 32);
        float4 u30 = __ldg(p3 + lane),      u31 = __ldg(p3 + lane + 32);
        acc4(a0, u00); acc4(a1, u01);
        acc4(a0, u10); acc4(a1, u11);
        acc4(a0, u20); acc4(a1, u21);
        acc4(a0, u30); acc4(a1, u31);
    }
    for (; e < end; e++) {
        int s = __ldg(ssrc + e);
        const float4* p = (const float4*)(x + (size_t)s * D);
        acc4(a0, __ldg(p + lane));
        acc4(a1, __ldg(p + lane + 32));
    }

    const float inv = 1.0f / fmaxf((float)deg, 1.0f);
    a0.x *= inv; a0.y *= inv; a0.z *= inv; a0.w *= inv;
    a1.x *= inv; a1.y *= inv; a1.z *= inv; a1.w *= inv;

    const float4* pt = (const float4*)(x + (size_t)d * D);
    float4 t0 = __ldg(pt + lane), t1 = __ldg(pt + lane + 32);

    ushort4 h, l;
    __nv_bfloat16* row = Aexp + (size_t)d * KSTORE;
    split4(a0, h, l);
    *(ushort4*)(row +   0 + 4 * lane) = h;  *(ushort4*)(row + 512 + 4 * lane) = l;
    split4(a1, h, l);
    *(ushort4*)(row + 128 + 4 * lane) = h;  *(ushort4*)(row + 640 + 4 * lane) = l;
    split4(t0, h, l);
    *(ushort4*)(row + 256 + 4 * lane) = h;  *(ushort4*)(row + 768 + 4 * lane) = l;
    split4(t1, h, l);
    *(ushort4*)(row + 384 + 4 * lane) = h;  *(ushort4*)(row + 896 + 4 * lane) = l;
}

// ---------------- weight prep (both layers, one launch) ----------------
__global__ void wprep2_kernel(const float* __restrict__ Wl1, const float* __restrict__ Wr1,
                              __nv_bfloat16* __restrict__ Wb1,
                              const float* __restrict__ Wl2, const float* __restrict__ Wr2,
                              __nv_bfloat16* __restrict__ Wb2) {
    int i = blockIdx.x * blockDim.x + threadIdx.x;
    if (i >= 2 * D * 512) return;
    const float* Wl = (i < D * 512) ? Wl1 : Wl2;
    const float* Wr = (i < D * 512) ? Wr1 : Wr2;
    __nv_bfloat16* Wb = (i < D * 512) ? Wb1 : Wb2;
    int j = (i < D * 512) ? i : (i - D * 512);
    int n = j / 512, k = j % 512;
    float w = (k < D) ? Wl[n * D + k] : Wr[n * D + (k - D)];
    __nv_bfloat16 hi = __float2bfloat16(w);
    __nv_bfloat16 lo = __float2bfloat16(w - __bfloat162float(hi));
    __nv_bfloat16* row = Wb + (size_t)n * KEXP;
    row[k]        = hi;
    row[512 + k]  = lo;
    row[1024 + k] = hi;
}

// ---------------- mma.sync bf16 GEMM (R13-proven: BM=128, BN=128, 256 thr) -------
__global__ __launch_bounds__(256, 1)
void sage_mma_gemm(const __nv_bfloat16* __restrict__ Aexp,
                   const __nv_bfloat16* __restrict__ Wb,
                   const float* __restrict__ bias,
                   float* __restrict__ out, int M) {
    extern __shared__ __align__(1024) char smem[];
    const uint32_t TILES = (smem_u32(smem) + 1023u) & ~1023u;

    const int tid  = threadIdx.x;
    const int wid  = tid >> 5;
    const int lane = tid & 31;
    const int wm   = wid & 3;
    const int wn   = wid >> 2;
    const int row0 = blockIdx.x * BM;
    const int col0 = blockIdx.y * BN;

    const int ld_r = tid >> 3;
    const int ld_q = tid & 7;

    uint32_t aPart[2], bPart[4];
    {
        int r  = (lane & 15);
        int hb = (lane >> 4) * 16;
        #pragma unroll
        for (int mi = 0; mi < 2; mi++)
            aPart[mi] = (uint32_t)((wm * 32 + mi * 16 + r) * 128 + hb);
        #pragma unroll
        for (int g = 0; g < 4; g++)
            bPart[g] = (uint32_t)((wn * 64 + g * 16 + r) * 128 + hb);
    }

    float acc[2][8][4];
    #pragma unroll
    for (int mi = 0; mi < 2; mi++)
        #pragma unroll
        for (int ni = 0; ni < 8; ni++)
            #pragma unroll
            for (int t = 0; t < 4; t++) acc[mi][ni][t] = 0.0f;

    auto load_chunk = [&](int c) {
        const int s  = c % STAGES;
        const int kb = c * KC;
        const int ka = (kb < 512) ? kb : kb - 512;
        const uint32_t sA = TILES + s * STAGE_BYTES;
        const uint32_t sB = sA + BM * 128;
        #pragma unroll
        for (int i = 0; i < 4; i++) {
            int m = ld_r + i * 32;
            int gr = row0 + m; if (gr > M - 1) gr = M - 1;
            cp_async16(sA + SWZ(m * 128 + ld_q * 16),
                       Aexp + (size_t)gr * KSTORE + ka + ld_q * 8);
        }
        #pragma unroll
        for (int i = 0; i < 4; i++) {
            int n = ld_r + i * 32;
            cp_async16(sB + SWZ(n * 128 + ld_q * 16),
                       Wb + (size_t)(col0 + n) * KEXP + kb + ld_q * 8);
        }
        CP_COMMIT();
    };

    load_chunk(0);
    load_chunk(1);

    #pragma unroll 1
    for (int c = 0; c < NCHUNK; c++) {
        if (c == NCHUNK - 1) { CP_WAIT(0); } else { CP_WAIT(1); }
        __syncthreads();
        if (c + 2 < NCHUNK) load_chunk(c + 2);

        const uint32_t sA = TILES + (c % STAGES) * STAGE_BYTES;
        const uint32_t sB = sA + BM * 128;

        #pragma unroll
        for (int ks = 0; ks < 4; ks++) {
            const uint32_t kadv = ks * 32;
            uint32_t a[2][4];
            #pragma unroll
            for (int mi = 0; mi < 2; mi++)
                ldsm_x4(a[mi][0], a[mi][1], a[mi][2], a[mi][3],
                        sA + SWZ(aPart[mi] + kadv));
            uint32_t b[8][2];
            #pragma unroll
            for (int g = 0; g < 4; g++) {
                uint32_t r0, r1, r2, r3;
                ldsm_x4(r0, r1, r2, r3, sB + SWZ(bPart[g] + kadv));
                b[2*g][0] = r0;  b[2*g+1][0] = r1;
                b[2*g][1] = r2;  b[2*g+1][1] = r3;
            }
            #pragma unroll
            for (int mi = 0; mi < 2; mi++)
                #pragma unroll
                for (int ni = 0; ni < 8; ni++)
                    mma_bf16(acc[mi][ni],
                             a[mi][0], a[mi][1], a[mi][2], a[mi][3],
                             b[ni][0], b[ni][1]);
        }
    }

    const int rbase = row0 + wm * 32 + (lane >> 2);
    const int cbase = col0 + wn * 64 + 2 * (lane & 3);
    #pragma unroll
    for (int ni = 0; ni < 8; ni++) {
        const int col = cbase + ni * 8;
        const float2 bv = *(const float2*)(bias + col);
        #pragma unroll
        for (int mi = 0; mi < 2; mi++) {
            int r = rbase + mi * 16;
            if (r < M) {
                float2 o;
                o.x = tanhf(acc[mi][ni][0] + bv.x);
                o.y = tanhf(acc[mi][ni][1] + bv.y);
                *(float2*)(out + (size_t)r * D + col) = o;
            }
            if (r + 8 < M) {
                float2 o;
                o.x = tanhf(acc[mi][ni][2] + bv.x);
                o.y = tanhf(acc[mi][ni][3] + bv.y);
                *(float2*)(out + (size_t)(r + 8) * D + col) = o;
            }
        }
    }
}

// ---------------- launch ----------------
extern "C" void kernel_launch(void* const* d_in, const int* in_sizes, int n_in,
                              void* d_out, int out_size) {
    const float* nodes = (const float*)d_in[0];
    const float* Wl1   = (const float*)d_in[1];
    const float* b1    = (const float*)d_in[2];
    const float* Wr1   = (const float*)d_in[3];
    const float* Wl2   = (const float*)d_in[4];
    const float* b2    = (const float*)d_in[5];
    const float* Wr2   = (const float*)d_in[6];
    const int*   src1  = (const int*)d_in[7];
    const int*   dst1  = (const int*)d_in[8];
    const int*   src2  = (const int*)d_in[9];
    const int*   dst2  = (const int*)d_in[10];
    const int E1 = in_sizes[7];
    const int E2 = in_sizes[9];

    float *p_h1;
    __nv_bfloat16 *p_Aexp, *p_Wb1, *p_Wb2;
    int *p_cur, *p_ssrc;
    cudaGetSymbolAddress((void**)&p_h1,   g_h1);
    cudaGetSymbolAddress((void**)&p_Aexp, g_Aexp);
    cudaGetSymbolAddress((void**)&p_Wb1,  g_Wb1);
    cudaGetSymbolAddress((void**)&p_Wb2,  g_Wb2);
    cudaGetSymbolAddress((void**)&p_cur,  g_cur);
    cudaGetSymbolAddress((void**)&p_ssrc, g_ssrc);

    cudaFuncSetAttribute(sage_mma_gemm, cudaFuncAttributeMaxDynamicSharedMemorySize,
                         SMEM_BYTES);

    wprep2_kernel<<<(2 * D * 512 + 255) / 256, 256>>>(Wl1, Wr1, p_Wb1, Wl2, Wr2, p_Wb2);

    // ---- direct bucket binning for both layers (cur zero at entry) ----
    bin12_kernel<<<(E1 + E2 + 255) / 256, 256>>>(src1, dst1, E1, src2, dst2, E2,
                                                 p_cur, p_ssrc);

    // ---- layer 1 ----
    agg_prep_kernel<<<(N1C * 32 + 255) / 256, 256>>>(nodes, p_cur, p_ssrc,
                                                     p_Aexp, N1C, 0);
    {
        dim3 grid((N1C + BM - 1) / BM, 2);
        sage_mma_gemm<<<grid, 256, SMEM_BYTES>>>(p_Aexp, p_Wb1, b1, p_h1, N1C);
    }

    // ---- layer 2 ----
    agg_prep_kernel<<<(N2C * 32 + 255) / 256, 256>>>(p_h1, p_cur, p_ssrc,
                                                     p_Aexp, N2C, N1C);
    {
        dim3 grid((N2C + BM - 1) / BM, 2);
        sage_mma_gemm<<<grid, 256, SMEM_BYTES>>>(p_Aexp, p_Wb2, b2, (float*)d_out, N2C);
    }
}

// round 15
// speedup vs baseline: 1.2259x; 1.2259x over previous
#include <cuda_runtime.h>
#include <cuda_bf16.h>
#include <math.h>
#include <stdint.h>

#define D      256
#define N1C    40000
#define N2C    8000
#define NTOT   (N1C + N2C)
#define E1MAX  1000000
#define E2MAX  200000
#define KEXP   1536          // expanded K:  [Ah|Ah|Al] x [Wh;Wl;Wh]
#define KSTORE 1024          // Aexp stored dedup'd: [Ah|Al]
#define BM     128
#define BN     128
#define KC     64
#define NCHUNK 24            // 1536/64
#define STAGES 3
#define STAGE_BYTES (BM*128 + BN*128)       // 32 KB
#define SMEM_BYTES  (STAGES*STAGE_BYTES + 1024)
#define SCAN_BLK 256

// ---------------- scratch ----------------
__device__ float g_h1[(size_t)N1C * D];
__device__ __nv_bfloat16 g_Aexp[(size_t)N1C * KSTORE];   // 81.9 MB (reused layer 2)
__device__ __nv_bfloat16 g_Wb1[(size_t)D * KEXP];
__device__ __nv_bfloat16 g_Wb2[(size_t)D * KEXP];
__device__ int g_hist[NTOT];         // zero at steady state (self-cleaning)
__device__ int g_off[NTOT];
__device__ int g_cur[NTOT];
__device__ int g_ssrc[E1MAX + E2MAX];
__device__ int g_counter[1];         // zero at steady state (self-cleaning)

// ---------------- helpers ----------------
__device__ __forceinline__ uint32_t smem_u32(const void* p) {
    uint32_t a;
    asm("{ .reg .u64 t; cvta.to.shared.u64 t, %1; cvt.u32.u64 %0, t; }"
        : "=r"(a) : "l"(p));
    return a;
}
#define SWZ(o) ((o) ^ (((o) >> 3) & 0x70))

__device__ __forceinline__ void cp_async16(uint32_t dst, const void* src) {
    asm volatile("cp.async.cg.shared.global [%0], [%1], 16;" :: "r"(dst), "l"(src));
}
#define CP_COMMIT()  asm volatile("cp.async.commit_group;")
#define CP_WAIT(n)   asm volatile("cp.async.wait_group %0;" :: "n"(n))

__device__ __forceinline__ void ldsm_x4(uint32_t& r0, uint32_t& r1,
                                        uint32_t& r2, uint32_t& r3, uint32_t addr) {
    asm volatile("ldmatrix.sync.aligned.m8n8.x4.shared.b16 {%0,%1,%2,%3}, [%4];"
                 : "=r"(r0), "=r"(r1), "=r"(r2), "=r"(r3) : "r"(addr));
}
__device__ __forceinline__ void mma_bf16(float* c,
        uint32_t a0, uint32_t a1, uint32_t a2, uint32_t a3,
        uint32_t b0, uint32_t b1) {
    asm volatile(
        "mma.sync.aligned.m16n8k16.row.col.f32.bf16.bf16.f32 "
        "{%0,%1,%2,%3}, {%4,%5,%6,%7}, {%8,%9}, {%0,%1,%2,%3};"
        : "+f"(c[0]), "+f"(c[1]), "+f"(c[2]), "+f"(c[3])
        : "r"(a0), "r"(a1), "r"(a2), "r"(a3), "r"(b0), "r"(b1));
}

// ---------------- fused cross-layer binning (1 edge/thread — R13-proven) ----------
// Combined index space: layer-1 dst in [0,N1C), layer-2 dst in [N1C, NTOT).
__global__ void hist12_kernel(const int* __restrict__ dst1, int E1,
                              const int* __restrict__ dst2, int E2,
                              int* __restrict__ hist) {
    const int t = blockIdx.x * blockDim.x + threadIdx.x;
    if (t < E1)            atomicAdd(hist + __ldg(dst1 + t), 1);
    else if (t < E1 + E2)  atomicAdd(hist + N1C + __ldg(dst2 + (t - E1)), 1);
}

// Single-kernel unordered partition (block scan + atomic base). Self-cleans hist.
__global__ void alloc_kernel(int* __restrict__ hist, int* __restrict__ off,
                             int* __restrict__ cur, int* __restrict__ counter, int n) {
    __shared__ int sh[SCAN_BLK];
    __shared__ int base;
    const int t = threadIdx.x;
    const int i = blockIdx.x * SCAN_BLK + t;
    const int v = (i < n) ? hist[i] : 0;
    sh[t] = v;
    __syncthreads();
    #pragma unroll
    for (int d = 1; d < SCAN_BLK; d <<= 1) {
        int u = (t >= d) ? sh[t - d] : 0;
        __syncthreads();
        sh[t] += u;
        __syncthreads();
    }
    if (t == SCAN_BLK - 1) base = atomicAdd(counter, sh[SCAN_BLK - 1]);
    __syncthreads();
    const int o = base + sh[t] - v;
    if (i < n) { off[i] = o; cur[i] = o; hist[i] = 0; }
}

__global__ void bin12_kernel(const int* __restrict__ src1, const int* __restrict__ dst1, int E1,
                             const int* __restrict__ src2, const int* __restrict__ dst2, int E2,
                             int* __restrict__ cur, int* __restrict__ ssrc,
                             int* __restrict__ counter) {
    const int t = blockIdx.x * blockDim.x + threadIdx.x;
    if (t == 0) counter[0] = 0;      // consumed by alloc; reset for next replay
    if (t < E1) {
        int p = atomicAdd(cur + __ldg(dst1 + t), 1);
        ssrc[p] = __ldg(src1 + t);
    } else if (t < E1 + E2) {
        int e = t - E1;
        int p = atomicAdd(cur + N1C + __ldg(dst2 + e), 1);
        ssrc[p] = __ldg(src2 + e);
    }
}

// ---------------- fused aggregation + mean + bf16-split prep (R10-proven) ----------------
__device__ __forceinline__ void split4(float4 v, ushort4& hi, ushort4& lo) {
    float f[4] = {v.x, v.y, v.z, v.w};
    unsigned short* hp = &hi.x;
    unsigned short* lp = &lo.x;
    #pragma unroll
    for (int t = 0; t < 4; t++) {
        __nv_bfloat16 h = __float2bfloat16(f[t]);
        __nv_bfloat16 l = __float2bfloat16(f[t] - __bfloat162float(h));
        hp[t] = *(unsigned short*)&h;
        lp[t] = *(unsigned short*)&l;
    }
}
__device__ __forceinline__ void acc4(float4& a, float4 v) {
    a.x += v.x; a.y += v.y; a.z += v.z; a.w += v.w;
}

__global__ void agg_prep_kernel(const float* __restrict__ x,
                                const int* __restrict__ off,
                                const int* __restrict__ cur,
                                const int* __restrict__ ssrc,
                                __nv_bfloat16* __restrict__ Aexp, int n) {
    const int d = (blockIdx.x * blockDim.x + threadIdx.x) >> 5;
    const int lane = threadIdx.x & 31;
    if (d >= n) return;
    const int beg = __ldg(off + d);
    const int end = __ldg(cur + d);

    float4 a0 = make_float4(0, 0, 0, 0), a1 = make_float4(0, 0, 0, 0);
    int e = beg;
    for (; e + 4 <= end; e += 4) {
        int s0 = __ldg(ssrc + e + 0);
        int s1 = __ldg(ssrc + e + 1);
        int s2 = __ldg(ssrc + e + 2);
        int s3 = __ldg(ssrc + e + 3);
        const float4* p0 = (const float4*)(x + (size_t)s0 * D);
        const float4* p1 = (const float4*)(x + (size_t)s1 * D);
        const float4* p2 = (const float4*)(x + (size_t)s2 * D);
        const float4* p3 = (const float4*)(x + (size_t)s3 * D);
        float4 u00 = __ldg(p0 + lane),      u01 = __ldg(p0 + lane + 32);
        float4 u10 = __ldg(p1 + lane),      u11 = __ldg(p1 + lane + 32);
        float4 u20 = __ldg(p2 + lane),      u21 = __ldg(p2 + lane + 32);
        float4 u30 = __ldg(p3 + lane),      u31 = __ldg(p3 + lane + 32);
        acc4(a0, u00); acc4(a1, u01);
        acc4(a0, u10); acc4(a1, u11);
        acc4(a0, u20); acc4(a1, u21);
        acc4(a0, u30); acc4(a1, u31);
    }
    for (; e < end; e++) {
        int s = __ldg(ssrc + e);
        const float4* p = (const float4*)(x + (size_t)s * D);
        acc4(a0, __ldg(p + lane));
        acc4(a1, __ldg(p + lane + 32));
    }

    const float inv = 1.0f / fmaxf((float)(end - beg), 1.0f);
    a0.x *= inv; a0.y *= inv; a0.z *= inv; a0.w *= inv;
    a1.x *= inv; a1.y *= inv; a1.z *= inv; a1.w *= inv;

    const float4* pt = (const float4*)(x + (size_t)d * D);
    float4 t0 = __ldg(pt + lane), t1 = __ldg(pt + lane + 32);

    ushort4 h, l;
    __nv_bfloat16* row = Aexp + (size_t)d * KSTORE;
    split4(a0, h, l);
    *(ushort4*)(row +   0 + 4 * lane) = h;  *(ushort4*)(row + 512 + 4 * lane) = l;
    split4(a1, h, l);
    *(ushort4*)(row + 128 + 4 * lane) = h;  *(ushort4*)(row + 640 + 4 * lane) = l;
    split4(t0, h, l);
    *(ushort4*)(row + 256 + 4 * lane) = h;  *(ushort4*)(row + 768 + 4 * lane) = l;
    split4(t1, h, l);
    *(ushort4*)(row + 384 + 4 * lane) = h;  *(ushort4*)(row + 896 + 4 * lane) = l;
}

// ---------------- weight prep (both layers, one launch) ----------------
__global__ void wprep2_kernel(const float* __restrict__ Wl1, const float* __restrict__ Wr1,
                              __nv_bfloat16* __restrict__ Wb1,
                              const float* __restrict__ Wl2, const float* __restrict__ Wr2,
                              __nv_bfloat16* __restrict__ Wb2) {
    int i = blockIdx.x * blockDim.x + threadIdx.x;
    if (i >= 2 * D * 512) return;
    const float* Wl = (i < D * 512) ? Wl1 : Wl2;
    const float* Wr = (i < D * 512) ? Wr1 : Wr2;
    __nv_bfloat16* Wb = (i < D * 512) ? Wb1 : Wb2;
    int j = (i < D * 512) ? i : (i - D * 512);
    int n = j / 512, k = j % 512;
    float w = (k < D) ? Wl[n * D + k] : Wr[n * D + (k - D)];
    __nv_bfloat16 hi = __float2bfloat16(w);
    __nv_bfloat16 lo = __float2bfloat16(w - __bfloat162float(hi));
    __nv_bfloat16* row = Wb + (size_t)n * KEXP;
    row[k]        = hi;
    row[512 + k]  = lo;
    row[1024 + k] = hi;
}

// ---------------- mma.sync bf16 GEMM — now 2 CTAs/SM (reg cap 128) ----------------
__global__ __launch_bounds__(256, 2)
void sage_mma_gemm(const __nv_bfloat16* __restrict__ Aexp,
                   const __nv_bfloat16* __restrict__ Wb,
                   const float* __restrict__ bias,
                   float* __restrict__ out, int M) {
    extern __shared__ __align__(1024) char smem[];
    const uint32_t TILES = (smem_u32(smem) + 1023u) & ~1023u;

    const int tid  = threadIdx.x;
    const int wid  = tid >> 5;
    const int lane = tid & 31;
    const int wm   = wid & 3;
    const int wn   = wid >> 2;
    const int row0 = blockIdx.x * BM;
    const int col0 = blockIdx.y * BN;

    const int ld_r = tid >> 3;
    const int ld_q = tid & 7;

    uint32_t aPart[2], bPart[4];
    {
        int r  = (lane & 15);
        int hb = (lane >> 4) * 16;
        #pragma unroll
        for (int mi = 0; mi < 2; mi++)
            aPart[mi] = (uint32_t)((wm * 32 + mi * 16 + r) * 128 + hb);
        #pragma unroll
        for (int g = 0; g < 4; g++)
            bPart[g] = (uint32_t)((wn * 64 + g * 16 + r) * 128 + hb);
    }

    float acc[2][8][4];
    #pragma unroll
    for (int mi = 0; mi < 2; mi++)
        #pragma unroll
        for (int ni = 0; ni < 8; ni++)
            #pragma unroll
            for (int t = 0; t < 4; t++) acc[mi][ni][t] = 0.0f;

    auto load_chunk = [&](int c) {
        const int s  = c % STAGES;
        const int kb = c * KC;
        const int ka = (kb < 512) ? kb : kb - 512;
        const uint32_t sA = TILES + s * STAGE_BYTES;
        const uint32_t sB = sA + BM * 128;
        #pragma unroll
        for (int i = 0; i < 4; i++) {
            int m = ld_r + i * 32;
            int gr = row0 + m; if (gr > M - 1) gr = M - 1;
            cp_async16(sA + SWZ(m * 128 + ld_q * 16),
                       Aexp + (size_t)gr * KSTORE + ka + ld_q * 8);
        }
        #pragma unroll
        for (int i = 0; i < 4; i++) {
            int n = ld_r + i * 32;
            cp_async16(sB + SWZ(n * 128 + ld_q * 16),
                       Wb + (size_t)(col0 + n) * KEXP + kb + ld_q * 8);
        }
        CP_COMMIT();
    };

    load_chunk(0);
    load_chunk(1);

    #pragma unroll 1
    for (int c = 0; c < NCHUNK; c++) {
        if (c == NCHUNK - 1) { CP_WAIT(0); } else { CP_WAIT(1); }
        __syncthreads();
        if (c + 2 < NCHUNK) load_chunk(c + 2);

        const uint32_t sA = TILES + (c % STAGES) * STAGE_BYTES;
        const uint32_t sB = sA + BM * 128;

        #pragma unroll
        for (int ks = 0; ks < 4; ks++) {
            const uint32_t kadv = ks * 32;
            uint32_t a[2][4];
            #pragma unroll
            for (int mi = 0; mi < 2; mi++)
                ldsm_x4(a[mi][0], a[mi][1], a[mi][2], a[mi][3],
                        sA + SWZ(aPart[mi] + kadv));
            uint32_t b[8][2];
            #pragma unroll
            for (int g = 0; g < 4; g++) {
                uint32_t r0, r1, r2, r3;
                ldsm_x4(r0, r1, r2, r3, sB + SWZ(bPart[g] + kadv));
                b[2*g][0] = r0;  b[2*g+1][0] = r1;
                b[2*g][1] = r2;  b[2*g+1][1] = r3;
            }
            #pragma unroll
            for (int mi = 0; mi < 2; mi++)
                #pragma unroll
                for (int ni = 0; ni < 8; ni++)
                    mma_bf16(acc[mi][ni],
                             a[mi][0], a[mi][1], a[mi][2], a[mi][3],
                             b[ni][0], b[ni][1]);
        }
    }

    const int rbase = row0 + wm * 32 + (lane >> 2);
    const int cbase = col0 + wn * 64 + 2 * (lane & 3);
    #pragma unroll
    for (int ni = 0; ni < 8; ni++) {
        const int col = cbase + ni * 8;
        const float2 bv = *(const float2*)(bias + col);
        #pragma unroll
        for (int mi = 0; mi < 2; mi++) {
            int r = rbase + mi * 16;
            if (r < M) {
                float2 o;
                o.x = tanhf(acc[mi][ni][0] + bv.x);
                o.y = tanhf(acc[mi][ni][1] + bv.y);
                *(float2*)(out + (size_t)r * D + col) = o;
            }
            if (r + 8 < M) {
                float2 o;
                o.x = tanhf(acc[mi][ni][2] + bv.x);
                o.y = tanhf(acc[mi][ni][3] + bv.y);
                *(float2*)(out + (size_t)(r + 8) * D + col) = o;
            }
        }
    }
}

// ---------------- launch ----------------
extern "C" void kernel_launch(void* const* d_in, const int* in_sizes, int n_in,
                              void* d_out, int out_size) {
    const float* nodes = (const float*)d_in[0];
    const float* Wl1   = (const float*)d_in[1];
    const float* b1    = (const float*)d_in[2];
    const float* Wr1   = (const float*)d_in[3];
    const float* Wl2   = (const float*)d_in[4];
    const float* b2    = (const float*)d_in[5];
    const float* Wr2   = (const float*)d_in[6];
    const int*   src1  = (const int*)d_in[7];
    const int*   dst1  = (const int*)d_in[8];
    const int*   src2  = (const int*)d_in[9];
    const int*   dst2  = (const int*)d_in[10];
    const int E1 = in_sizes[7];
    const int E2 = in_sizes[9];

    float *p_h1;
    __nv_bfloat16 *p_Aexp, *p_Wb1, *p_Wb2;
    int *p_hist, *p_off, *p_cur, *p_ssrc, *p_counter;
    cudaGetSymbolAddress((void**)&p_h1,      g_h1);
    cudaGetSymbolAddress((void**)&p_Aexp,    g_Aexp);
    cudaGetSymbolAddress((void**)&p_Wb1,     g_Wb1);
    cudaGetSymbolAddress((void**)&p_Wb2,     g_Wb2);
    cudaGetSymbolAddress((void**)&p_hist,    g_hist);
    cudaGetSymbolAddress((void**)&p_off,     g_off);
    cudaGetSymbolAddress((void**)&p_cur,     g_cur);
    cudaGetSymbolAddress((void**)&p_ssrc,    g_ssrc);
    cudaGetSymbolAddress((void**)&p_counter, g_counter);

    cudaFuncSetAttribute(sage_mma_gemm, cudaFuncAttributeMaxDynamicSharedMemorySize,
                         SMEM_BYTES);

    wprep2_kernel<<<(2 * D * 512 + 255) / 256, 256>>>(Wl1, Wr1, p_Wb1, Wl2, Wr2, p_Wb2);

    // ---- fused binning for both layers (hist/counter zero at entry) ----
    {
        const int tt = E1 + E2;
        hist12_kernel<<<(tt + 255) / 256, 256>>>(dst1, E1, dst2, E2, p_hist);
        alloc_kernel<<<(NTOT + SCAN_BLK - 1) / SCAN_BLK, SCAN_BLK>>>(
            p_hist, p_off, p_cur, p_counter, NTOT);
        bin12_kernel<<<(tt + 255) / 256, 256>>>(src1, dst1, E1, src2, dst2, E2,
                                                p_cur, p_ssrc, p_counter);
    }

    // ---- layer 1 ----
    agg_prep_kernel<<<(N1C * 32 + 255) / 256, 256>>>(nodes, p_off, p_cur, p_ssrc,
                                                     p_Aexp, N1C);
    {
        dim3 grid((N1C + BM - 1) / BM, 2);
        sage_mma_gemm<<<grid, 256, SMEM_BYTES>>>(p_Aexp, p_Wb1, b1, p_h1, N1C);
    }

    // ---- layer 2 ----
    agg_prep_kernel<<<(N2C * 32 + 255) / 256, 256>>>(p_h1, p_off + N1C, p_cur + N1C,
                                                     p_ssrc, p_Aexp, N2C);
    {
        dim3 grid((N2C + BM - 1) / BM, 2);
        sage_mma_gemm<<<grid, 256, SMEM_BYTES>>>(p_Aexp, p_Wb2, b2, (float*)d_out, N2C);
    }
}

// round 16
// speedup vs baseline: 1.2588x; 1.0269x over previous
#include <cuda_runtime.h>
#include <cuda_bf16.h>
#include <math.h>
#include <stdint.h>

#define D      256
#define N1C    40000
#define N2C    8000
#define NTOT   (N1C + N2C)
#define E1MAX  1000000
#define E2MAX  200000
#define KEXP   1536          // expanded K:  [Ah|Ah|Al] x [Wh;Wl;Wh]
#define KSTORE 1024          // Aexp stored dedup'd: [Ah|Al]
#define BM     64
#define BN     128
#define KC     64
#define NCHUNK 24            // 1536/64
#define STAGES 3
#define STAGE_BYTES (BM*128 + BN*128)       // 24 KB
#define SMEM_BYTES  (STAGES*STAGE_BYTES + 1024)
#define SCAN_BLK 256

// ---------------- scratch ----------------
__device__ float g_h1[(size_t)N1C * D];
__device__ __nv_bfloat16 g_Aexp[(size_t)N1C * KSTORE];   // 81.9 MB (reused layer 2)
__device__ __nv_bfloat16 g_Wb1[(size_t)D * KEXP];
__device__ __nv_bfloat16 g_Wb2[(size_t)D * KEXP];
__device__ int g_hist[NTOT];         // zero at steady state (self-cleaning)
__device__ int g_off[NTOT];
__device__ int g_cur[NTOT];
__device__ int g_ssrc[E1MAX + E2MAX];
__device__ int g_counter[1];         // zero at steady state (self-cleaning)

// ---------------- helpers ----------------
__device__ __forceinline__ uint32_t smem_u32(const void* p) {
    uint32_t a;
    asm("{ .reg .u64 t; cvta.to.shared.u64 t, %1; cvt.u32.u64 %0, t; }"
        : "=r"(a) : "l"(p));
    return a;
}
#define SWZ(o) ((o) ^ (((o) >> 3) & 0x70))

__device__ __forceinline__ void cp_async16(uint32_t dst, const void* src) {
    asm volatile("cp.async.cg.shared.global [%0], [%1], 16;" :: "r"(dst), "l"(src));
}
#define CP_COMMIT()  asm volatile("cp.async.commit_group;")
#define CP_WAIT(n)   asm volatile("cp.async.wait_group %0;" :: "n"(n))

__device__ __forceinline__ void ldsm_x4(uint32_t& r0, uint32_t& r1,
                                        uint32_t& r2, uint32_t& r3, uint32_t addr) {
    asm volatile("ldmatrix.sync.aligned.m8n8.x4.shared.b16 {%0,%1,%2,%3}, [%4];"
                 : "=r"(r0), "=r"(r1), "=r"(r2), "=r"(r3) : "r"(addr));
}
__device__ __forceinline__ void mma_bf16(float* c,
        uint32_t a0, uint32_t a1, uint32_t a2, uint32_t a3,
        uint32_t b0, uint32_t b1) {
    asm volatile(
        "mma.sync.aligned.m16n8k16.row.col.f32.bf16.bf16.f32 "
        "{%0,%1,%2,%3}, {%4,%5,%6,%7}, {%8,%9}, {%0,%1,%2,%3};"
        : "+f"(c[0]), "+f"(c[1]), "+f"(c[2]), "+f"(c[3])
        : "r"(a0), "r"(a1), "r"(a2), "r"(a3), "r"(b0), "r"(b1));
}

// ---------------- fused cross-layer binning (1 edge/thread — R13-proven) ----------
__global__ void hist12_kernel(const int* __restrict__ dst1, int E1,
                              const int* __restrict__ dst2, int E2,
                              int* __restrict__ hist) {
    const int t = blockIdx.x * blockDim.x + threadIdx.x;
    if (t < E1)            atomicAdd(hist + __ldg(dst1 + t), 1);
    else if (t < E1 + E2)  atomicAdd(hist + N1C + __ldg(dst2 + (t - E1)), 1);
}

__global__ void alloc_kernel(int* __restrict__ hist, int* __restrict__ off,
                             int* __restrict__ cur, int* __restrict__ counter, int n) {
    __shared__ int sh[SCAN_BLK];
    __shared__ int base;
    const int t = threadIdx.x;
    const int i = blockIdx.x * SCAN_BLK + t;
    const int v = (i < n) ? hist[i] : 0;
    sh[t] = v;
    __syncthreads();
    #pragma unroll
    for (int d = 1; d < SCAN_BLK; d <<= 1) {
        int u = (t >= d) ? sh[t - d] : 0;
        __syncthreads();
        sh[t] += u;
        __syncthreads();
    }
    if (t == SCAN_BLK - 1) base = atomicAdd(counter, sh[SCAN_BLK - 1]);
    __syncthreads();
    const int o = base + sh[t] - v;
    if (i < n) { off[i] = o; cur[i] = o; hist[i] = 0; }
}

__global__ void bin12_kernel(const int* __restrict__ src1, const int* __restrict__ dst1, int E1,
                             const int* __restrict__ src2, const int* __restrict__ dst2, int E2,
                             int* __restrict__ cur, int* __restrict__ ssrc,
                             int* __restrict__ counter) {
    const int t = blockIdx.x * blockDim.x + threadIdx.x;
    if (t == 0) counter[0] = 0;      // consumed by alloc; reset for next replay
    if (t < E1) {
        int p = atomicAdd(cur + __ldg(dst1 + t), 1);
        ssrc[p] = __ldg(src1 + t);
    } else if (t < E1 + E2) {
        int e = t - E1;
        int p = atomicAdd(cur + N1C + __ldg(dst2 + e), 1);
        ssrc[p] = __ldg(src2 + e);
    }
}

// ---------------- fused aggregation + mean + bf16-split prep (R10-proven) ----------------
__device__ __forceinline__ void split4(float4 v, ushort4& hi, ushort4& lo) {
    float f[4] = {v.x, v.y, v.z, v.w};
    unsigned short* hp = &hi.x;
    unsigned short* lp = &lo.x;
    #pragma unroll
    for (int t = 0; t < 4; t++) {
        __nv_bfloat16 h = __float2bfloat16(f[t]);
        __nv_bfloat16 l = __float2bfloat16(f[t] - __bfloat162float(h));
        hp[t] = *(unsigned short*)&h;
        lp[t] = *(unsigned short*)&l;
    }
}
__device__ __forceinline__ void acc4(float4& a, float4 v) {
    a.x += v.x; a.y += v.y; a.z += v.z; a.w += v.w;
}

__global__ void agg_prep_kernel(const float* __restrict__ x,
                                const int* __restrict__ off,
                                const int* __restrict__ cur,
                                const int* __restrict__ ssrc,
                                __nv_bfloat16* __restrict__ Aexp, int n) {
    const int d = (blockIdx.x * blockDim.x + threadIdx.x) >> 5;
    const int lane = threadIdx.x & 31;
    if (d >= n) return;
    const int beg = __ldg(off + d);
    const int end = __ldg(cur + d);

    float4 a0 = make_float4(0, 0, 0, 0), a1 = make_float4(0, 0, 0, 0);
    int e = beg;
    for (; e + 4 <= end; e += 4) {
        int s0 = __ldg(ssrc + e + 0);
        int s1 = __ldg(ssrc + e + 1);
        int s2 = __ldg(ssrc + e + 2);
        int s3 = __ldg(ssrc + e + 3);
        const float4* p0 = (const float4*)(x + (size_t)s0 * D);
        const float4* p1 = (const float4*)(x + (size_t)s1 * D);
        const float4* p2 = (const float4*)(x + (size_t)s2 * D);
        const float4* p3 = (const float4*)(x + (size_t)s3 * D);
        float4 u00 = __ldg(p0 + lane),      u01 = __ldg(p0 + lane + 32);
        float4 u10 = __ldg(p1 + lane),      u11 = __ldg(p1 + lane + 32);
        float4 u20 = __ldg(p2 + lane),      u21 = __ldg(p2 + lane + 32);
        float4 u30 = __ldg(p3 + lane),      u31 = __ldg(p3 + lane + 32);
        acc4(a0, u00); acc4(a1, u01);
        acc4(a0, u10); acc4(a1, u11);
        acc4(a0, u20); acc4(a1, u21);
        acc4(a0, u30); acc4(a1, u31);
    }
    for (; e < end; e++) {
        int s = __ldg(ssrc + e);
        const float4* p = (const float4*)(x + (size_t)s * D);
        acc4(a0, __ldg(p + lane));
        acc4(a1, __ldg(p + lane + 32));
    }

    const float inv = 1.0f / fmaxf((float)(end - beg), 1.0f);
    a0.x *= inv; a0.y *= inv; a0.z *= inv; a0.w *= inv;
    a1.x *= inv; a1.y *= inv; a1.z *= inv; a1.w *= inv;

    const float4* pt = (const float4*)(x + (size_t)d * D);
    float4 t0 = __ldg(pt + lane), t1 = __ldg(pt + lane + 32);

    ushort4 h, l;
    __nv_bfloat16* row = Aexp + (size_t)d * KSTORE;
    split4(a0, h, l);
    *(ushort4*)(row +   0 + 4 * lane) = h;  *(ushort4*)(row + 512 + 4 * lane) = l;
    split4(a1, h, l);
    *(ushort4*)(row + 128 + 4 * lane) = h;  *(ushort4*)(row + 640 + 4 * lane) = l;
    split4(t0, h, l);
    *(ushort4*)(row + 256 + 4 * lane) = h;  *(ushort4*)(row + 768 + 4 * lane) = l;
    split4(t1, h, l);
    *(ushort4*)(row + 384 + 4 * lane) = h;  *(ushort4*)(row + 896 + 4 * lane) = l;
}

// ---------------- weight prep (both layers, one launch) ----------------
__global__ void wprep2_kernel(const float* __restrict__ Wl1, const float* __restrict__ Wr1,
                              __nv_bfloat16* __restrict__ Wb1,
                              const float* __restrict__ Wl2, const float* __restrict__ Wr2,
                              __nv_bfloat16* __restrict__ Wb2) {
    int i = blockIdx.x * blockDim.x + threadIdx.x;
    if (i >= 2 * D * 512) return;
    const float* Wl = (i < D * 512) ? Wl1 : Wl2;
    const float* Wr = (i < D * 512) ? Wr1 : Wr2;
    __nv_bfloat16* Wb = (i < D * 512) ? Wb1 : Wb2;
    int j = (i < D * 512) ? i : (i - D * 512);
    int n = j / 512, k = j % 512;
    float w = (k < D) ? Wl[n * D + k] : Wr[n * D + (k - D)];
    __nv_bfloat16 hi = __float2bfloat16(w);
    __nv_bfloat16 lo = __float2bfloat16(w - __bfloat162float(hi));
    __nv_bfloat16* row = Wb + (size_t)n * KEXP;
    row[k]        = hi;
    row[512 + k]  = lo;
    row[1024 + k] = hi;
}

// ---------------- mma.sync bf16 GEMM — BM=64, 4 warps (2x2), 3 CTAs/SM ----------------
// grid = (2, ceil(M/64)): blockIdx.x = column half (schedule-adjacent for A L2 reuse).
__global__ __launch_bounds__(128, 3)
void sage_mma_gemm(const __nv_bfloat16* __restrict__ Aexp,
                   const __nv_bfloat16* __restrict__ Wb,
                   const float* __restrict__ bias,
                   float* __restrict__ out, int M) {
    extern __shared__ __align__(1024) char smem[];
    const uint32_t TILES = (smem_u32(smem) + 1023u) & ~1023u;

    const int tid  = threadIdx.x;
    const int wid  = tid >> 5;
    const int lane = tid & 31;
    const int wm   = wid & 1;           // 2 warps along M
    const int wn   = wid >> 1;          // 2 warps along N
    const int row0 = blockIdx.y * BM;
    const int col0 = blockIdx.x * BN;

    const int ld_r = tid >> 3;          // 0..15
    const int ld_q = tid & 7;

    uint32_t aPart[2], bPart[4];
    {
        int r  = (lane & 15);
        int hb = (lane >> 4) * 16;
        #pragma unroll
        for (int mi = 0; mi < 2; mi++)
            aPart[mi] = (uint32_t)((wm * 32 + mi * 16 + r) * 128 + hb);
        #pragma unroll
        for (int g = 0; g < 4; g++)
            bPart[g] = (uint32_t)((wn * 64 + g * 16 + r) * 128 + hb);
    }

    float acc[2][8][4];
    #pragma unroll
    for (int mi = 0; mi < 2; mi++)
        #pragma unroll
        for (int ni = 0; ni < 8; ni++)
            #pragma unroll
            for (int t = 0; t < 4; t++) acc[mi][ni][t] = 0.0f;

    auto load_chunk = [&](int c) {
        const int s  = c % STAGES;
        const int kb = c * KC;
        const int ka = (kb < 512) ? kb : kb - 512;
        const uint32_t sA = TILES + s * STAGE_BYTES;
        const uint32_t sB = sA + BM * 128;
        #pragma unroll
        for (int i = 0; i < 4; i++) {       // A: 64 rows x 8 quads / 128 thr
            int m = ld_r + i * 16;
            int gr = row0 + m; if (gr > M - 1) gr = M - 1;
            cp_async16(sA + SWZ(m * 128 + ld_q * 16),
                       Aexp + (size_t)gr * KSTORE + ka + ld_q * 8);
        }
        #pragma unroll
        for (int i = 0; i < 8; i++) {       // B: 128 rows x 8 quads / 128 thr
            int n = ld_r + i * 16;
            cp_async16(sB + SWZ(n * 128 + ld_q * 16),
                       Wb + (size_t)(col0 + n) * KEXP + kb + ld_q * 8);
        }
        CP_COMMIT();
    };

    load_chunk(0);
    load_chunk(1);

    #pragma unroll 1
    for (int c = 0; c < NCHUNK; c++) {
        if (c == NCHUNK - 1) { CP_WAIT(0); } else { CP_WAIT(1); }
        __syncthreads();
        if (c + 2 < NCHUNK) load_chunk(c + 2);

        const uint32_t sA = TILES + (c % STAGES) * STAGE_BYTES;
        const uint32_t sB = sA + BM * 128;

        #pragma unroll
        for (int ks = 0; ks < 4; ks++) {
            const uint32_t kadv = ks * 32;
            uint32_t a[2][4];
            #pragma unroll
            for (int mi = 0; mi < 2; mi++)
                ldsm_x4(a[mi][0], a[mi][1], a[mi][2], a[mi][3],
                        sA + SWZ(aPart[mi] + kadv));
            uint32_t b[8][2];
            #pragma unroll
            for (int g = 0; g < 4; g++) {
                uint32_t r0, r1, r2, r3;
                ldsm_x4(r0, r1, r2, r3, sB + SWZ(bPart[g] + kadv));
                b[2*g][0] = r0;  b[2*g+1][0] = r1;
                b[2*g][1] = r2;  b[2*g+1][1] = r3;
            }
            #pragma unroll
            for (int mi = 0; mi < 2; mi++)
                #pragma unroll
                for (int ni = 0; ni < 8; ni++)
                    mma_bf16(acc[mi][ni],
                             a[mi][0], a[mi][1], a[mi][2], a[mi][3],
                             b[ni][0], b[ni][1]);
        }
    }

    const int rbase = row0 + wm * 32 + (lane >> 2);
    const int cbase = col0 + wn * 64 + 2 * (lane & 3);
    #pragma unroll
    for (int ni = 0; ni < 8; ni++) {
        const int col = cbase + ni * 8;
        const float2 bv = *(const float2*)(bias + col);
        #pragma unroll
        for (int mi = 0; mi < 2; mi++) {
            int r = rbase + mi * 16;
            if (r < M) {
                float2 o;
                o.x = tanhf(acc[mi][ni][0] + bv.x);
                o.y = tanhf(acc[mi][ni][1] + bv.y);
                *(float2*)(out + (size_t)r * D + col) = o;
            }
            if (r + 8 < M) {
                float2 o;
                o.x = tanhf(acc[mi][ni][2] + bv.x);
                o.y = tanhf(acc[mi][ni][3] + bv.y);
                *(float2*)(out + (size_t)(r + 8) * D + col) = o;
            }
        }
    }
}

// ---------------- launch ----------------
extern "C" void kernel_launch(void* const* d_in, const int* in_sizes, int n_in,
                              void* d_out, int out_size) {
    const float* nodes = (const float*)d_in[0];
    const float* Wl1   = (const float*)d_in[1];
    const float* b1    = (const float*)d_in[2];
    const float* Wr1   = (const float*)d_in[3];
    const float* Wl2   = (const float*)d_in[4];
    const float* b2    = (const float*)d_in[5];
    const float* Wr2   = (const float*)d_in[6];
    const int*   src1  = (const int*)d_in[7];
    const int*   dst1  = (const int*)d_in[8];
    const int*   src2  = (const int*)d_in[9];
    const int*   dst2  = (const int*)d_in[10];
    const int E1 = in_sizes[7];
    const int E2 = in_sizes[9];

    float *p_h1;
    __nv_bfloat16 *p_Aexp, *p_Wb1, *p_Wb2;
    int *p_hist, *p_off, *p_cur, *p_ssrc, *p_counter;
    cudaGetSymbolAddress((void**)&p_h1,      g_h1);
    cudaGetSymbolAddress((void**)&p_Aexp,    g_Aexp);
    cudaGetSymbolAddress((void**)&p_Wb1,     g_Wb1);
    cudaGetSymbolAddress((void**)&p_Wb2,     g_Wb2);
    cudaGetSymbolAddress((void**)&p_hist,    g_hist);
    cudaGetSymbolAddress((void**)&p_off,     g_off);
    cudaGetSymbolAddress((void**)&p_cur,     g_cur);
    cudaGetSymbolAddress((void**)&p_ssrc,    g_ssrc);
    cudaGetSymbolAddress((void**)&p_counter, g_counter);

    cudaFuncSetAttribute(sage_mma_gemm, cudaFuncAttributeMaxDynamicSharedMemorySize,
                         SMEM_BYTES);

    wprep2_kernel<<<(2 * D * 512 + 255) / 256, 256>>>(Wl1, Wr1, p_Wb1, Wl2, Wr2, p_Wb2);

    // ---- fused binning for both layers (hist/counter zero at entry) ----
    {
        const int tt = E1 + E2;
        hist12_kernel<<<(tt + 255) / 256, 256>>>(dst1, E1, dst2, E2, p_hist);
        alloc_kernel<<<(NTOT + SCAN_BLK - 1) / SCAN_BLK, SCAN_BLK>>>(
            p_hist, p_off, p_cur, p_counter, NTOT);
        bin12_kernel<<<(tt + 255) / 256, 256>>>(src1, dst1, E1, src2, dst2, E2,
                                                p_cur, p_ssrc, p_counter);
    }

    // ---- layer 1 ----
    agg_prep_kernel<<<(N1C * 32 + 255) / 256, 256>>>(nodes, p_off, p_cur, p_ssrc,
                                                     p_Aexp, N1C);
    {
        dim3 grid(2, (N1C + BM - 1) / BM);
        sage_mma_gemm<<<grid, 128, SMEM_BYTES>>>(p_Aexp, p_Wb1, b1, p_h1, N1C);
    }

    // ---- layer 2 ----
    agg_prep_kernel<<<(N2C * 32 + 255) / 256, 256>>>(p_h1, p_off + N1C, p_cur + N1C,
                                                     p_ssrc, p_Aexp, N2C);
    {
        dim3 grid(2, (N2C + BM - 1) / BM);
        sage_mma_gemm<<<grid, 128, SMEM_BYTES>>>(p_Aexp, p_Wb2, b2, (float*)d_out, N2C);
    }
}

// round 17
// speedup vs baseline: 1.2775x; 1.0149x over previous
#include <cuda_runtime.h>
#include <cuda_bf16.h>
#include <math.h>
#include <stdint.h>

#define D      256
#define N1C    40000
#define N2C    8000
#define NTOT   (N1C + N2C)
#define E1MAX  1000000
#define E2MAX  200000
#define KEXP   1536          // expanded K:  [Ah|Ah|Al] x [Wh;Wl;Wh]
#define KSTORE 1024          // Aexp stored dedup'd: [Ah|Al]
#define BM     64
#define BN     128
#define KC     64
#define NCHUNK 24            // 1536/64
#define STAGES 3
#define STAGE_BYTES (BM*128 + BN*128)       // 24 KB
#define SMEM_BYTES  (STAGES*STAGE_BYTES + 1024)
#define SCAN_BLK 256
#define WPREP_N (2 * D * 512)               // 262144

// ---------------- scratch ----------------
__device__ float g_h1[(size_t)N1C * D];
__device__ __nv_bfloat16 g_Aexp[(size_t)N1C * KSTORE];   // 81.9 MB (reused layer 2)
__device__ __nv_bfloat16 g_Wb1[(size_t)D * KEXP];
__device__ __nv_bfloat16 g_Wb2[(size_t)D * KEXP];
__device__ int g_hist[NTOT];         // zero at steady state (self-cleaning)
__device__ int g_off[NTOT];
__device__ int g_cur[NTOT];          // holds segment END after alloc
__device__ int g_rank[E1MAX + E2MAX];
__device__ int g_ssrc[E1MAX + E2MAX];
__device__ int g_counter[1];         // zero at steady state (self-cleaning)

// ---------------- helpers ----------------
__device__ __forceinline__ uint32_t smem_u32(const void* p) {
    uint32_t a;
    asm("{ .reg .u64 t; cvta.to.shared.u64 t, %1; cvt.u32.u64 %0, t; }"
        : "=r"(a) : "l"(p));
    return a;
}
#define SWZ(o) ((o) ^ (((o) >> 3) & 0x70))

__device__ __forceinline__ void cp_async16(uint32_t dst, const void* src) {
    asm volatile("cp.async.cg.shared.global [%0], [%1], 16;" :: "r"(dst), "l"(src));
}
#define CP_COMMIT()  asm volatile("cp.async.commit_group;")
#define CP_WAIT(n)   asm volatile("cp.async.wait_group %0;" :: "n"(n))

__device__ __forceinline__ void ldsm_x4(uint32_t& r0, uint32_t& r1,
                                        uint32_t& r2, uint32_t& r3, uint32_t addr) {
    asm volatile("ldmatrix.sync.aligned.m8n8.x4.shared.b16 {%0,%1,%2,%3}, [%4];"
                 : "=r"(r0), "=r"(r1), "=r"(r2), "=r"(r3) : "r"(addr));
}
__device__ __forceinline__ void mma_bf16(float* c,
        uint32_t a0, uint32_t a1, uint32_t a2, uint32_t a3,
        uint32_t b0, uint32_t b1) {
    asm volatile(
        "mma.sync.aligned.m16n8k16.row.col.f32.bf16.bf16.f32 "
        "{%0,%1,%2,%3}, {%4,%5,%6,%7}, {%8,%9}, {%0,%1,%2,%3};"
        : "+f"(c[0]), "+f"(c[1]), "+f"(c[2]), "+f"(c[3])
        : "r"(a0), "r"(a1), "r"(a2), "r"(a3), "r"(b0), "r"(b1));
}

// fast tanh: clamp ±8 (tanh(8)=1-4.5e-7), e=exp(2x), (e-1)/(e+1)
__device__ __forceinline__ float fast_tanh(float x) {
    float cx = fminf(fmaxf(x, -8.0f), 8.0f);
    float e  = __expf(2.0f * cx);
    return __fdividef(e - 1.0f, e + 1.0f);
}

// ---------------- fused weight-prep + hist + rank ----------------
// grid spans E1+E2 edge threads; threads [0, WPREP_N) also do weight prep.
__global__ void prep_hist_kernel(
    const float* __restrict__ Wl1, const float* __restrict__ Wr1,
    __nv_bfloat16* __restrict__ Wb1,
    const float* __restrict__ Wl2, const float* __restrict__ Wr2,
    __nv_bfloat16* __restrict__ Wb2,
    const int* __restrict__ dst1, int E1,
    const int* __restrict__ dst2, int E2,
    int* __restrict__ hist, int* __restrict__ rank) {
    const int t = blockIdx.x * blockDim.x + threadIdx.x;

    if (t < WPREP_N) {
        const float* Wl = (t < D * 512) ? Wl1 : Wl2;
        const float* Wr = (t < D * 512) ? Wr1 : Wr2;
        __nv_bfloat16* Wb = (t < D * 512) ? Wb1 : Wb2;
        int j = (t < D * 512) ? t : (t - D * 512);
        int n = j / 512, k = j % 512;
        float w = (k < D) ? Wl[n * D + k] : Wr[n * D + (k - D)];
        __nv_bfloat16 hi = __float2bfloat16(w);
        __nv_bfloat16 lo = __float2bfloat16(w - __bfloat162float(hi));
        __nv_bfloat16* row = Wb + (size_t)n * KEXP;
        row[k]        = hi;
        row[512 + k]  = lo;
        row[1024 + k] = hi;
    }

    if (t < E1) {
        int r = atomicAdd(hist + __ldg(dst1 + t), 1);
        rank[t] = r;
    } else if (t < E1 + E2) {
        int e = t - E1;
        int r = atomicAdd(hist + N1C + __ldg(dst2 + e), 1);
        rank[t] = r;
    }
}

// Unordered partition: off = segment begin, cur = segment END. Self-cleans hist.
__global__ void alloc_kernel(int* __restrict__ hist, int* __restrict__ off,
                             int* __restrict__ cur, int* __restrict__ counter, int n) {
    __shared__ int sh[SCAN_BLK];
    __shared__ int base;
    const int t = threadIdx.x;
    const int i = blockIdx.x * SCAN_BLK + t;
    const int v = (i < n) ? hist[i] : 0;
    sh[t] = v;
    __syncthreads();
    #pragma unroll
    for (int d = 1; d < SCAN_BLK; d <<= 1) {
        int u = (t >= d) ? sh[t - d] : 0;
        __syncthreads();
        sh[t] += u;
        __syncthreads();
    }
    if (t == SCAN_BLK - 1) base = atomicAdd(counter, sh[SCAN_BLK - 1]);
    __syncthreads();
    const int o = base + sh[t] - v;
    if (i < n) { off[i] = o; cur[i] = o + v; hist[i] = 0; }
}

// bin: atomic-free — placement = off[dst] + precomputed rank. Pure streaming.
__global__ void bin12_kernel(const int* __restrict__ src1, const int* __restrict__ dst1, int E1,
                             const int* __restrict__ src2, const int* __restrict__ dst2, int E2,
                             const int* __restrict__ off, const int* __restrict__ rank,
                             int* __restrict__ ssrc, int* __restrict__ counter) {
    const int t = blockIdx.x * blockDim.x + threadIdx.x;
    if (t == 0) counter[0] = 0;      // consumed by alloc; reset for next replay
    if (t < E1) {
        int d = __ldg(dst1 + t);
        ssrc[__ldg(off + d) + __ldg(rank + t)] = __ldg(src1 + t);
    } else if (t < E1 + E2) {
        int e = t - E1;
        int d = N1C + __ldg(dst2 + e);
        ssrc[__ldg(off + d) + __ldg(rank + t)] = __ldg(src2 + e);
    }
}

// ---------------- fused aggregation + mean + bf16-split prep (R10-proven) ----------------
__device__ __forceinline__ void split4(float4 v, ushort4& hi, ushort4& lo) {
    float f[4] = {v.x, v.y, v.z, v.w};
    unsigned short* hp = &hi.x;
    unsigned short* lp = &lo.x;
    #pragma unroll
    for (int t = 0; t < 4; t++) {
        __nv_bfloat16 h = __float2bfloat16(f[t]);
        __nv_bfloat16 l = __float2bfloat16(f[t] - __bfloat162float(h));
        hp[t] = *(unsigned short*)&h;
        lp[t] = *(unsigned short*)&l;
    }
}
__device__ __forceinline__ void acc4(float4& a, float4 v) {
    a.x += v.x; a.y += v.y; a.z += v.z; a.w += v.w;
}

__global__ void agg_prep_kernel(const float* __restrict__ x,
                                const int* __restrict__ off,
                                const int* __restrict__ cur,
                                const int* __restrict__ ssrc,
                                __nv_bfloat16* __restrict__ Aexp, int n) {
    const int d = (blockIdx.x * blockDim.x + threadIdx.x) >> 5;
    const int lane = threadIdx.x & 31;
    if (d >= n) return;
    const int beg = __ldg(off + d);
    const int end = __ldg(cur + d);      // alloc wrote begin+degree

    float4 a0 = make_float4(0, 0, 0, 0), a1 = make_float4(0, 0, 0, 0);
    int e = beg;
    for (; e + 4 <= end; e += 4) {
        int s0 = __ldg(ssrc + e + 0);
        int s1 = __ldg(ssrc + e + 1);
        int s2 = __ldg(ssrc + e + 2);
        int s3 = __ldg(ssrc + e + 3);
        const float4* p0 = (const float4*)(x + (size_t)s0 * D);
        const float4* p1 = (const float4*)(x + (size_t)s1 * D);
        const float4* p2 = (const float4*)(x + (size_t)s2 * D);
        const float4* p3 = (const float4*)(x + (size_t)s3 * D);
        float4 u00 = __ldg(p0 + lane),      u01 = __ldg(p0 + lane + 32);
        float4 u10 = __ldg(p1 + lane),      u11 = __ldg(p1 + lane + 32);
        float4 u20 = __ldg(p2 + lane),      u21 = __ldg(p2 + lane + 32);
        float4 u30 = __ldg(p3 + lane),      u31 = __ldg(p3 + lane + 32);
        acc4(a0, u00); acc4(a1, u01);
        acc4(a0, u10); acc4(a1, u11);
        acc4(a0, u20); acc4(a1, u21);
        acc4(a0, u30); acc4(a1, u31);
    }
    for (; e < end; e++) {
        int s = __ldg(ssrc + e);
        const float4* p = (const float4*)(x + (size_t)s * D);
        acc4(a0, __ldg(p + lane));
        acc4(a1, __ldg(p + lane + 32));
    }

    const float inv = 1.0f / fmaxf((float)(end - beg), 1.0f);
    a0.x *= inv; a0.y *= inv; a0.z *= inv; a0.w *= inv;
    a1.x *= inv; a1.y *= inv; a1.z *= inv; a1.w *= inv;

    const float4* pt = (const float4*)(x + (size_t)d * D);
    float4 t0 = __ldg(pt + lane), t1 = __ldg(pt + lane + 32);

    ushort4 h, l;
    __nv_bfloat16* row = Aexp + (size_t)d * KSTORE;
    split4(a0, h, l);
    *(ushort4*)(row +   0 + 4 * lane) = h;  *(ushort4*)(row + 512 + 4 * lane) = l;
    split4(a1, h, l);
    *(ushort4*)(row + 128 + 4 * lane) = h;  *(ushort4*)(row + 640 + 4 * lane) = l;
    split4(t0, h, l);
    *(ushort4*)(row + 256 + 4 * lane) = h;  *(ushort4*)(row + 768 + 4 * lane) = l;
    split4(t1, h, l);
    *(ushort4*)(row + 384 + 4 * lane) = h;  *(ushort4*)(row + 896 + 4 * lane) = l;
}

// ---------------- mma.sync bf16 GEMM (R16-proven: BM=64, 4 warps, 3 CTAs/SM) -------
__global__ __launch_bounds__(128, 3)
void sage_mma_gemm(const __nv_bfloat16* __restrict__ Aexp,
                   const __nv_bfloat16* __restrict__ Wb,
                   const float* __restrict__ bias,
                   float* __restrict__ out, int M) {
    extern __shared__ __align__(1024) char smem[];
    const uint32_t TILES = (smem_u32(smem) + 1023u) & ~1023u;

    const int tid  = threadIdx.x;
    const int wid  = tid >> 5;
    const int lane = tid & 31;
    const int wm   = wid & 1;
    const int wn   = wid >> 1;
    const int row0 = blockIdx.y * BM;
    const int col0 = blockIdx.x * BN;

    const int ld_r = tid >> 3;
    const int ld_q = tid & 7;

    uint32_t aPart[2], bPart[4];
    {
        int r  = (lane & 15);
        int hb = (lane >> 4) * 16;
        #pragma unroll
        for (int mi = 0; mi < 2; mi++)
            aPart[mi] = (uint32_t)((wm * 32 + mi * 16 + r) * 128 + hb);
        #pragma unroll
        for (int g = 0; g < 4; g++)
            bPart[g] = (uint32_t)((wn * 64 + g * 16 + r) * 128 + hb);
    }

    float acc[2][8][4];
    #pragma unroll
    for (int mi = 0; mi < 2; mi++)
        #pragma unroll
        for (int ni = 0; ni < 8; ni++)
            #pragma unroll
            for (int t = 0; t < 4; t++) acc[mi][ni][t] = 0.0f;

    auto load_chunk = [&](int c) {
        const int s  = c % STAGES;
        const int kb = c * KC;
        const int ka = (kb < 512) ? kb : kb - 512;
        const uint32_t sA = TILES + s * STAGE_BYTES;
        const uint32_t sB = sA + BM * 128;
        #pragma unroll
        for (int i = 0; i < 4; i++) {
            int m = ld_r + i * 16;
            int gr = row0 + m; if (gr > M - 1) gr = M - 1;
            cp_async16(sA + SWZ(m * 128 + ld_q * 16),
                       Aexp + (size_t)gr * KSTORE + ka + ld_q * 8);
        }
        #pragma unroll
        for (int i = 0; i < 8; i++) {
            int n = ld_r + i * 16;
            cp_async16(sB + SWZ(n * 128 + ld_q * 16),
                       Wb + (size_t)(col0 + n) * KEXP + kb + ld_q * 8);
        }
        CP_COMMIT();
    };

    load_chunk(0);
    load_chunk(1);

    #pragma unroll 1
    for (int c = 0; c < NCHUNK; c++) {
        if (c == NCHUNK - 1) { CP_WAIT(0); } else { CP_WAIT(1); }
        __syncthreads();
        if (c + 2 < NCHUNK) load_chunk(c + 2);

        const uint32_t sA = TILES + (c % STAGES) * STAGE_BYTES;
        const uint32_t sB = sA + BM * 128;

        #pragma unroll
        for (int ks = 0; ks < 4; ks++) {
            const uint32_t kadv = ks * 32;
            uint32_t a[2][4];
            #pragma unroll
            for (int mi = 0; mi < 2; mi++)
                ldsm_x4(a[mi][0], a[mi][1], a[mi][2], a[mi][3],
                        sA + SWZ(aPart[mi] + kadv));
            uint32_t b[8][2];
            #pragma unroll
            for (int g = 0; g < 4; g++) {
                uint32_t r0, r1, r2, r3;
                ldsm_x4(r0, r1, r2, r3, sB + SWZ(bPart[g] + kadv));
                b[2*g][0] = r0;  b[2*g+1][0] = r1;
                b[2*g][1] = r2;  b[2*g+1][1] = r3;
            }
            #pragma unroll
            for (int mi = 0; mi < 2; mi++)
                #pragma unroll
                for (int ni = 0; ni < 8; ni++)
                    mma_bf16(acc[mi][ni],
                             a[mi][0], a[mi][1], a[mi][2], a[mi][3],
                             b[ni][0], b[ni][1]);
        }
    }

    const int rbase = row0 + wm * 32 + (lane >> 2);
    const int cbase = col0 + wn * 64 + 2 * (lane & 3);
    #pragma unroll
    for (int ni = 0; ni < 8; ni++) {
        const int col = cbase + ni * 8;
        const float2 bv = *(const float2*)(bias + col);
        #pragma unroll
        for (int mi = 0; mi < 2; mi++) {
            int r = rbase + mi * 16;
            if (r < M) {
                float2 o;
                o.x = fast_tanh(acc[mi][ni][0] + bv.x);
                o.y = fast_tanh(acc[mi][ni][1] + bv.y);
                *(float2*)(out + (size_t)r * D + col) = o;
            }
            if (r + 8 < M) {
                float2 o;
                o.x = fast_tanh(acc[mi][ni][2] + bv.x);
                o.y = fast_tanh(acc[mi][ni][3] + bv.y);
                *(float2*)(out + (size_t)(r + 8) * D + col) = o;
            }
        }
    }
}

// ---------------- launch ----------------
extern "C" void kernel_launch(void* const* d_in, const int* in_sizes, int n_in,
                              void* d_out, int out_size) {
    const float* nodes = (const float*)d_in[0];
    const float* Wl1   = (const float*)d_in[1];
    const float* b1    = (const float*)d_in[2];
    const float* Wr1   = (const float*)d_in[3];
    const float* Wl2   = (const float*)d_in[4];
    const float* b2    = (const float*)d_in[5];
    const float* Wr2   = (const float*)d_in[6];
    const int*   src1  = (const int*)d_in[7];
    const int*   dst1  = (const int*)d_in[8];
    const int*   src2  = (const int*)d_in[9];
    const int*   dst2  = (const int*)d_in[10];
    const int E1 = in_sizes[7];
    const int E2 = in_sizes[9];

    float *p_h1;
    __nv_bfloat16 *p_Aexp, *p_Wb1, *p_Wb2;
    int *p_hist, *p_off, *p_cur, *p_rank, *p_ssrc, *p_counter;
    cudaGetSymbolAddress((void**)&p_h1,      g_h1);
    cudaGetSymbolAddress((void**)&p_Aexp,    g_Aexp);
    cudaGetSymbolAddress((void**)&p_Wb1,     g_Wb1);
    cudaGetSymbolAddress((void**)&p_Wb2,     g_Wb2);
    cudaGetSymbolAddress((void**)&p_hist,    g_hist);
    cudaGetSymbolAddress((void**)&p_off,     g_off);
    cudaGetSymbolAddress((void**)&p_cur,     g_cur);
    cudaGetSymbolAddress((void**)&p_rank,    g_rank);
    cudaGetSymbolAddress((void**)&p_ssrc,    g_ssrc);
    cudaGetSymbolAddress((void**)&p_counter, g_counter);

    cudaFuncSetAttribute(sage_mma_gemm, cudaFuncAttributeMaxDynamicSharedMemorySize,
                         SMEM_BYTES);

    // ---- fused weight-prep + hist/rank, then alloc, then atomic-free bin ----
    {
        const int tt = (E1 + E2 > WPREP_N) ? (E1 + E2) : WPREP_N;
        prep_hist_kernel<<<(tt + 255) / 256, 256>>>(
            Wl1, Wr1, p_Wb1, Wl2, Wr2, p_Wb2, dst1, E1, dst2, E2, p_hist, p_rank);
        alloc_kernel<<<(NTOT + SCAN_BLK - 1) / SCAN_BLK, SCAN_BLK>>>(
            p_hist, p_off, p_cur, p_counter, NTOT);
        bin12_kernel<<<(E1 + E2 + 255) / 256, 256>>>(
            src1, dst1, E1, src2, dst2, E2, p_off, p_rank, p_ssrc, p_counter);
    }

    // ---- layer 1 ----
    agg_prep_kernel<<<(N1C * 32 + 255) / 256, 256>>>(nodes, p_off, p_cur, p_ssrc,
                                                     p_Aexp, N1C);
    {
        dim3 grid(2, (N1C + BM - 1) / BM);
        sage_mma_gemm<<<grid, 128, SMEM_BYTES>>>(p_Aexp, p_Wb1, b1, p_h1, N1C);
    }

    // ---- layer 2 ----
    agg_prep_kernel<<<(N2C * 32 + 255) / 256, 256>>>(p_h1, p_off + N1C, p_cur + N1C,
                                                     p_ssrc, p_Aexp, N2C);
    {
        dim3 grid(2, (N2C + BM - 1) / BM);
        sage_mma_gemm<<<grid, 128, SMEM_BYTES>>>(p_Aexp, p_Wb2, b2, (float*)d_out, N2C);
    }
}